// round 3
// baseline (speedup 1.0000x reference)
#include <cuda_runtime.h>

#define B_ 2
#define N_ 65536
#define C_ 256
#define H_ 8
#define D_ 64
#define S_ 64
#define TS 32            // tokens per chunk
#define PC 37            // CTAs per (b,h) pair -> 16*37 = 592 CTAs = 4 full waves
#define NCHUNK (N_/TS)   // 2048

// ---- scratch (no allocations allowed) ----
__device__ float g_T[B_*H_*S_*D_];     // unnormalized slice tokens
__device__ float g_norm[B_*H_*S_];     // slice weight sums
__device__ float g_We[H_*C_*S_];       // W_x(head) @ W_slice folded
__device__ float g_be[H_*S_];          // b_x(head) @ W_slice + b_slice

// K0: zero accumulators + fold effective slice weights
__global__ void prep_kernel(const float* __restrict__ W_x, const float* __restrict__ b_x,
                            const float* __restrict__ W_slice, const float* __restrict__ b_slice) {
    int idx = blockIdx.x * blockDim.x + threadIdx.x;   // 131072 threads
    if (idx < B_*H_*S_*D_) g_T[idx] = 0.f;
    if (idx < B_*H_*S_)    g_norm[idx] = 0.f;
    if (idx < H_*C_*S_) {
        int s = idx & 63, c = (idx >> 6) & 255, h = idx >> 14;
        float acc = 0.f;
        #pragma unroll
        for (int d = 0; d < 64; d++)
            acc += W_x[c*512 + h*64 + d] * W_slice[d*64 + s];
        g_We[idx] = acc;
    }
    if (idx < H_*S_) {
        int s = idx & 63, h = idx >> 6;
        float acc = b_slice[s];
        #pragma unroll
        for (int d = 0; d < 64; d++)
            acc += b_x[h*64 + d] * W_slice[d*64 + s];
        g_be[idx] = acc;
    }
}

// SMEM layout (floats):
//  sWe  [256][64]  @ 0       (16384)
//  sWfx [256][64]  @ 16384   (16384)
//  sX   [32][256]  @ 32768   (8192)
//  sF   [32][64]   @ 40960   (2048)
//  sW   [32][64]   @ 43008   (2048)   softmax weights
//  sBe  [64]       @ 45056
//  sBfx [64]       @ 45120
// total 45184 floats = 180736 B
#define SMEM_FLOATS 45184

extern __shared__ float sm[];

__global__ void __launch_bounds__(256, 1)
fused_kernel(const float* __restrict__ x, const float* __restrict__ W_fx,
             const float* __restrict__ b_fx, const float* __restrict__ temperature) {
    float* sWe  = sm;
    float* sWfx = sm + 16384;
    float* sX   = sm + 32768;
    float* sF   = sm + 40960;
    float* sW   = sm + 43008;
    float* sBe  = sm + 45056;
    float* sBfx = sm + 45120;

    const int tid  = threadIdx.x;
    const int pair = blockIdx.x / PC;      // b*8 + h
    const int cidx = blockIdx.x % PC;
    const int b = pair >> 3, h = pair & 7;

    // load per-head weights into SMEM (resident for whole kernel)
    for (int g = tid; g < 4096; g += 256) {
        ((float4*)sWe)[g] = ((const float4*)(g_We + h*16384))[g];
        int k = g >> 4, d4 = g & 15;
        *(float4*)&sWfx[k*64 + d4*4] = *(const float4*)&W_fx[k*512 + h*64 + d4*4];
    }
    if (tid < 64) {
        sBe[tid]  = g_be[h*64 + tid];
        sBfx[tid] = b_fx[h*64 + tid];
    }
    float tmp = temperature[h];
    tmp = fminf(fmaxf(tmp, 0.5f), 5.0f);
    const float invT = 1.0f / tmp;
    __syncthreads();

    const int warp = tid >> 5, lane = tid & 31;
    const int t0 = warp * 4;
    const int dcol = tid & 63, sbase = (tid >> 6) * 16;

    float accT[16];
    #pragma unroll
    for (int i = 0; i < 16; i++) accT[i] = 0.f;
    float accN = 0.f;

    const float* xbase = x + (size_t)b * N_ * C_;

    for (int chunk = cidx; chunk < NCHUNK; chunk += PC) {
        const float* xp = xbase + (size_t)chunk * TS * C_;

        // phase 1: load x tile (coalesced float4)
        for (int g = tid; g < 2048; g += 256)
            ((float4*)sX)[g] = ((const float4*)xp)[g];
        __syncthreads();

        // phase 2: per-warp, 4 tokens x (64 logit cols + 64 f cols)
        float accS[4][2], accF[4][2];
        #pragma unroll
        for (int i = 0; i < 4; i++) { accS[i][0]=accS[i][1]=accF[i][0]=accF[i][1]=0.f; }
        #pragma unroll 4
        for (int k = 0; k < 256; k++) {
            float2 we = *(const float2*)&sWe[k*64 + 2*lane];
            float2 wf = *(const float2*)&sWfx[k*64 + 2*lane];
            #pragma unroll
            for (int i = 0; i < 4; i++) {
                float xv = sX[(t0+i)*256 + k];
                accS[i][0] += xv * we.x;  accS[i][1] += xv * we.y;
                accF[i][0] += xv * wf.x;  accF[i][1] += xv * wf.y;
            }
        }

        // store f (+bias)
        float bf0 = sBfx[2*lane], bf1 = sBfx[2*lane+1];
        float be0 = sBe[2*lane],  be1 = sBe[2*lane+1];
        #pragma unroll
        for (int i = 0; i < 4; i++)
            *(float2*)&sF[(t0+i)*64 + 2*lane] = make_float2(accF[i][0]+bf0, accF[i][1]+bf1);

        // phase 3: softmax across 64 slices (spread 2-per-lane over the warp)
        #pragma unroll
        for (int i = 0; i < 4; i++) {
            float l0 = (accS[i][0] + be0) * invT;
            float l1 = (accS[i][1] + be1) * invT;
            float m = fmaxf(l0, l1);
            #pragma unroll
            for (int off = 16; off; off >>= 1)
                m = fmaxf(m, __shfl_xor_sync(0xffffffffu, m, off));
            float e0 = __expf(l0 - m), e1 = __expf(l1 - m);
            float ss = e0 + e1;
            #pragma unroll
            for (int off = 16; off; off >>= 1)
                ss += __shfl_xor_sync(0xffffffffu, ss, off);
            float inv = __frcp_rn(ss);
            *(float2*)&sW[(t0+i)*64 + 2*lane] = make_float2(e0*inv, e1*inv);
        }
        __syncthreads();

        // phase 4: rank-32 update of T[s][d] (16 s-rows per thread, in registers)
        #pragma unroll 4
        for (int t = 0; t < 32; t++) {
            float fv = sF[t*64 + dcol];
            const float4* wr = (const float4*)&sW[t*64 + sbase];
            float4 w0 = wr[0], w1 = wr[1], w2 = wr[2], w3 = wr[3];
            accT[0]  += w0.x*fv; accT[1]  += w0.y*fv; accT[2]  += w0.z*fv; accT[3]  += w0.w*fv;
            accT[4]  += w1.x*fv; accT[5]  += w1.y*fv; accT[6]  += w1.z*fv; accT[7]  += w1.w*fv;
            accT[8]  += w2.x*fv; accT[9]  += w2.y*fv; accT[10] += w2.z*fv; accT[11] += w2.w*fv;
            accT[12] += w3.x*fv; accT[13] += w3.y*fv; accT[14] += w3.z*fv; accT[15] += w3.w*fv;
        }
        if (tid < 64) {
            #pragma unroll
            for (int t = 0; t < 32; t++) accN += sW[t*64 + tid];
        }
        __syncthreads();
    }

    // flush partials
    float* dst = g_T + pair * 4096;
    #pragma unroll
    for (int i = 0; i < 16; i++)
        atomicAdd(&dst[(sbase + i)*64 + dcol], accT[i]);
    if (tid < 64) atomicAdd(&g_norm[pair*64 + tid], accN);
}

// K2: final normalization into the output buffer
__global__ void norm_kernel(float* __restrict__ out) {
    int idx = blockIdx.x * blockDim.x + threadIdx.x;   // 65536
    int ps = idx >> 6;                                 // pair*64 + s
    out[idx] = g_T[idx] / (g_norm[ps] + 0.01f);
}

extern "C" void kernel_launch(void* const* d_in, const int* in_sizes, int n_in,
                              void* d_out, int out_size) {
    const float* x    = (const float*)d_in[0];
    const float* W_x  = (const float*)d_in[1];
    const float* b_x  = (const float*)d_in[2];
    const float* W_fx = (const float*)d_in[3];
    const float* b_fx = (const float*)d_in[4];
    const float* W_s  = (const float*)d_in[5];
    const float* b_s  = (const float*)d_in[6];
    const float* temp = (const float*)d_in[7];
    float* out = (float*)d_out;

    cudaFuncSetAttribute(fused_kernel, cudaFuncAttributeMaxDynamicSharedMemorySize,
                         SMEM_FLOATS * (int)sizeof(float));

    prep_kernel<<<512, 256>>>(W_x, b_x, W_s, b_s);
    fused_kernel<<<16 * PC, 256, SMEM_FLOATS * sizeof(float)>>>(x, W_fx, b_fx, temp);
    norm_kernel<<<256, 256>>>(out);
}

// round 4
// speedup vs baseline: 2.4342x; 2.4342x over previous
#include <cuda_runtime.h>
#include <cstdint>

#define B_ 2
#define N_ 65536
#define C_ 256
#define H_ 8
#define D_ 64
#define S_ 64
#define TS 32            // tokens per chunk
#define PC 37            // CTAs per (b,h) pair -> 592 CTAs = 4 waves of 148
#define NCHUNK (N_/TS)   // 2048

// ---- scratch ----
__device__ float g_T[B_*H_*S_*D_];
__device__ float g_norm[B_*H_*S_];
__device__ float g_We[H_*C_*S_];       // W_x(head) @ W_slice folded (fp32)
__device__ float g_be[H_*S_];

// K0: zero accumulators + fold effective slice weights
__global__ void prep_kernel(const float* __restrict__ W_x, const float* __restrict__ b_x,
                            const float* __restrict__ W_slice, const float* __restrict__ b_slice) {
    int idx = blockIdx.x * blockDim.x + threadIdx.x;
    if (idx < B_*H_*S_*D_) g_T[idx] = 0.f;
    if (idx < B_*H_*S_)    g_norm[idx] = 0.f;
    if (idx < H_*C_*S_) {
        int s = idx & 63, c = (idx >> 6) & 255, h = idx >> 14;
        float acc = 0.f;
        #pragma unroll
        for (int d = 0; d < 64; d++)
            acc += W_x[c*512 + h*64 + d] * W_slice[d*64 + s];
        g_We[idx] = acc;
    }
    if (idx < H_*S_) {
        int s = idx & 63, h = idx >> 6;
        float acc = b_slice[s];
        #pragma unroll
        for (int d = 0; d < 64; d++)
            acc += b_x[h*64 + d] * W_slice[d*64 + s];
        g_be[idx] = acc;
    }
}

__device__ __forceinline__ uint32_t f2tf(float f) {
    uint32_t u;
    asm("cvt.rna.tf32.f32 %0, %1;" : "=r"(u) : "f"(f));
    return u;
}

__device__ __forceinline__ void mma_tf32(float* c, const uint32_t* a, const uint32_t* b) {
    asm volatile("mma.sync.aligned.m16n8k8.row.col.f32.tf32.tf32.f32 "
                 "{%0,%1,%2,%3},{%4,%5,%6,%7},{%8,%9},{%0,%1,%2,%3};"
                 : "+f"(c[0]), "+f"(c[1]), "+f"(c[2]), "+f"(c[3])
                 : "r"(a[0]), "r"(a[1]), "r"(a[2]), "r"(a[3]), "r"(b[0]), "r"(b[1]));
}

// SMEM layout (floats), pitches chosen for conflict-free mma fragment loads:
//  sWe  [256][72] @ 0       (18432)   tf32 bits
//  sWfx [256][72] @ 18432   (18432)   tf32 bits
//  sX   [32][260] @ 36864   (8320)    tf32 bits
//  sF   [32][72]  @ 45184   (2304)    tf32 bits (fx + bias)
//  sW   [32][72]  @ 47488   (2304)    fp32 logits -> tf32 softmax weights
//  sBe  [64]      @ 49792
//  sBfx [64]      @ 49856
#define SMEM_FLOATS 49920

extern __shared__ float sm[];

__global__ void __launch_bounds__(256, 1)
fused_kernel(const float* __restrict__ x, const float* __restrict__ W_fx,
             const float* __restrict__ b_fx, const float* __restrict__ temperature) {
    float* sWe  = sm;
    float* sWfx = sm + 18432;
    float* sX   = sm + 36864;
    float* sF   = sm + 45184;
    float* sWf  = sm + 47488;
    float* sBe  = sm + 49792;
    float* sBfx = sm + 49856;
    uint32_t* sWeU  = (uint32_t*)sWe;
    uint32_t* sWfxU = (uint32_t*)sWfx;
    uint32_t* sXu   = (uint32_t*)sX;
    uint32_t* sFu   = (uint32_t*)sF;
    uint32_t* sWu   = (uint32_t*)sWf;

    const int tid  = threadIdx.x;
    const int pair = blockIdx.x / PC;      // b*8 + h
    const int cidx = blockIdx.x % PC;
    const int b = pair >> 3, h = pair & 7;

    // stage weights (convert to tf32 once)
    for (int g = tid; g < 4096; g += 256) {
        int k = g >> 4, c4 = (g & 15) << 2;
        float4 we = *(const float4*)&g_We[h*16384 + k*64 + c4];
        uint4 ue; ue.x = f2tf(we.x); ue.y = f2tf(we.y); ue.z = f2tf(we.z); ue.w = f2tf(we.w);
        *(uint4*)&sWeU[k*72 + c4] = ue;
        float4 wf = *(const float4*)&W_fx[k*512 + h*64 + c4];
        uint4 uf; uf.x = f2tf(wf.x); uf.y = f2tf(wf.y); uf.z = f2tf(wf.z); uf.w = f2tf(wf.w);
        *(uint4*)&sWfxU[k*72 + c4] = uf;
    }
    if (tid < 64) {
        sBe[tid]  = g_be[h*64 + tid];
        sBfx[tid] = b_fx[h*64 + tid];
    }
    float tmp = temperature[h];
    tmp = fminf(fmaxf(tmp, 0.5f), 5.0f);
    const float invT = 1.0f / tmp;
    __syncthreads();

    const int warp = tid >> 5, lane = tid & 31;
    const int lg4 = lane >> 2, lm4 = lane & 3;

    // phase-2 role: warps 0-3 -> logits (We), warps 4-7 -> fx (Wfx); n0 = 16 cols each
    const int mat = warp >> 2;
    const int n0  = (warp & 3) * 16;
    const uint32_t* sWm = mat ? sWfxU : sWeU;

    // phase-4 role: warp -> s-tile (warp&3)*16, d-half (warp>>2)*32
    const int mt = warp & 3;
    const int nh = warp >> 2;

    float accT[4][4];
    #pragma unroll
    for (int i = 0; i < 4; i++)
        #pragma unroll
        for (int j = 0; j < 4; j++) accT[i][j] = 0.f;
    float accN = 0.f;

    const float* xbase = x + (size_t)b * N_ * C_;

    for (int chunk = cidx; chunk < NCHUNK; chunk += PC) {
        const float* xp = xbase + (size_t)chunk * TS * C_;

        // ---- phase 1: stage x tile (tf32) ----
        for (int g = tid; g < 2048; g += 256) {
            float4 v = ((const float4*)xp)[g];
            int row = g >> 6, c4 = (g & 63) << 2;
            uint4 u; u.x = f2tf(v.x); u.y = f2tf(v.y); u.z = f2tf(v.z); u.w = f2tf(v.w);
            *(uint4*)&sXu[row*260 + c4] = u;
        }
        __syncthreads();

        // ---- phase 2: [32 tok] x [64 cols], K=256 via tf32 mma ----
        float c2[2][2][4];
        #pragma unroll
        for (int m = 0; m < 2; m++)
            #pragma unroll
            for (int n = 0; n < 2; n++)
                #pragma unroll
                for (int j = 0; j < 4; j++) c2[m][n][j] = 0.f;

        #pragma unroll 8
        for (int k0 = 0; k0 < 256; k0 += 8) {
            uint32_t a[2][4];
            int ac = k0 + lm4;
            a[0][0] = sXu[lg4*260 + ac];
            a[0][1] = sXu[(lg4+8)*260 + ac];
            a[0][2] = sXu[lg4*260 + ac + 4];
            a[0][3] = sXu[(lg4+8)*260 + ac + 4];
            a[1][0] = sXu[(lg4+16)*260 + ac];
            a[1][1] = sXu[(lg4+24)*260 + ac];
            a[1][2] = sXu[(lg4+16)*260 + ac + 4];
            a[1][3] = sXu[(lg4+24)*260 + ac + 4];
            uint32_t bb[2][2];
            int bn = n0 + lg4;
            bb[0][0] = sWm[ac*72 + bn];
            bb[0][1] = sWm[(ac+4)*72 + bn];
            bb[1][0] = sWm[ac*72 + bn + 8];
            bb[1][1] = sWm[(ac+4)*72 + bn + 8];
            mma_tf32(c2[0][0], a[0], bb[0]);
            mma_tf32(c2[0][1], a[0], bb[1]);
            mma_tf32(c2[1][0], a[1], bb[0]);
            mma_tf32(c2[1][1], a[1], bb[1]);
        }

        // epilogue: logits -> sWf (raw fp32); fx -> sF (bias added, tf32)
        #pragma unroll
        for (int m = 0; m < 2; m++) {
            #pragma unroll
            for (int nt = 0; nt < 2; nt++) {
                int r = m*16 + lg4;
                int cc = n0 + nt*8 + (lm4 << 1);
                if (mat == 0) {
                    *(float2*)&sWf[r*72 + cc]     = make_float2(c2[m][nt][0], c2[m][nt][1]);
                    *(float2*)&sWf[(r+8)*72 + cc] = make_float2(c2[m][nt][2], c2[m][nt][3]);
                } else {
                    float2 bv = *(float2*)&sBfx[cc];
                    uint2 u0; u0.x = f2tf(c2[m][nt][0] + bv.x); u0.y = f2tf(c2[m][nt][1] + bv.y);
                    uint2 u1; u1.x = f2tf(c2[m][nt][2] + bv.x); u1.y = f2tf(c2[m][nt][3] + bv.y);
                    *(uint2*)&sFu[r*72 + cc]     = u0;
                    *(uint2*)&sFu[(r+8)*72 + cc] = u1;
                }
            }
        }
        __syncthreads();

        // ---- phase 3: softmax over 64 slices (warp handles 4 tokens) ----
        {
            float2 be = *(float2*)&sBe[lane << 1];
            #pragma unroll
            for (int i = 0; i < 4; i++) {
                int t = warp*4 + i;
                float2 lg = *(float2*)&sWf[t*72 + (lane << 1)];
                float l0 = (lg.x + be.x) * invT;
                float l1 = (lg.y + be.y) * invT;
                float m = fmaxf(l0, l1);
                #pragma unroll
                for (int off = 16; off; off >>= 1)
                    m = fmaxf(m, __shfl_xor_sync(0xffffffffu, m, off));
                float e0 = __expf(l0 - m), e1 = __expf(l1 - m);
                float ss = e0 + e1;
                #pragma unroll
                for (int off = 16; off; off >>= 1)
                    ss += __shfl_xor_sync(0xffffffffu, ss, off);
                float inv = __frcp_rn(ss);
                uint2 w2; w2.x = f2tf(e0 * inv); w2.y = f2tf(e1 * inv);
                *(uint2*)&sWu[t*72 + (lane << 1)] = w2;
            }
        }
        __syncthreads();

        // ---- phase 4: T[s][d] += W^T @ F via tf32 mma (acc persists in regs) ----
        #pragma unroll
        for (int k0 = 0; k0 < 32; k0 += 8) {
            uint32_t a[4];
            int at = k0 + lm4, as_ = mt*16 + lg4;
            a[0] = sWu[at*72 + as_];
            a[1] = sWu[at*72 + as_ + 8];
            a[2] = sWu[(at+4)*72 + as_];
            a[3] = sWu[(at+4)*72 + as_ + 8];
            #pragma unroll
            for (int nt = 0; nt < 4; nt++) {
                int d0 = nh*32 + nt*8 + lg4;
                uint32_t bb[2];
                bb[0] = sFu[at*72 + d0];
                bb[1] = sFu[(at+4)*72 + d0];
                mma_tf32(accT[nt], a, bb);
            }
        }
        // slice-norm partial sums (threads 0-63, conflict-free column reads)
        if (tid < 64) {
            #pragma unroll 8
            for (int t = 0; t < 32; t++) accN += sWf[t*72 + tid];
        }
        __syncthreads();
    }

    // ---- flush partials ----
    float* dst = g_T + pair * 4096;
    #pragma unroll
    for (int nt = 0; nt < 4; nt++) {
        int s0 = mt*16 + lg4;
        int d0 = nh*32 + nt*8 + (lm4 << 1);
        atomicAdd(&dst[s0*64 + d0],        accT[nt][0]);
        atomicAdd(&dst[s0*64 + d0 + 1],    accT[nt][1]);
        atomicAdd(&dst[(s0+8)*64 + d0],    accT[nt][2]);
        atomicAdd(&dst[(s0+8)*64 + d0+1],  accT[nt][3]);
    }
    if (tid < 64) atomicAdd(&g_norm[pair*64 + tid], accN);
}

// K2: final normalization
__global__ void norm_kernel(float* __restrict__ out) {
    int idx = blockIdx.x * blockDim.x + threadIdx.x;
    int ps = idx >> 6;
    out[idx] = g_T[idx] / (g_norm[ps] + 0.01f);
}

extern "C" void kernel_launch(void* const* d_in, const int* in_sizes, int n_in,
                              void* d_out, int out_size) {
    const float* x    = (const float*)d_in[0];
    const float* W_x  = (const float*)d_in[1];
    const float* b_x  = (const float*)d_in[2];
    const float* W_fx = (const float*)d_in[3];
    const float* b_fx = (const float*)d_in[4];
    const float* W_s  = (const float*)d_in[5];
    const float* b_s  = (const float*)d_in[6];
    const float* temp = (const float*)d_in[7];
    float* out = (float*)d_out;

    cudaFuncSetAttribute(fused_kernel, cudaFuncAttributeMaxDynamicSharedMemorySize,
                         SMEM_FLOATS * (int)sizeof(float));

    prep_kernel<<<512, 256>>>(W_x, b_x, W_s, b_s);
    fused_kernel<<<16 * PC, 256, SMEM_FLOATS * sizeof(float)>>>(x, W_fx, b_fx, temp);
    norm_kernel<<<256, 256>>>(out);
}

// round 8
// speedup vs baseline: 4.8670x; 1.9994x over previous
#include <cuda_runtime.h>
#include <cuda_fp16.h>
#include <cstdint>

#define B_ 2
#define N_ 65536
#define C_ 256
#define H_ 8
#define TS 32            // tokens per chunk
#define PC 37            // CTAs per (b,h) pair -> 592 CTAs
#define NCHUNK (N_/TS)   // 2048

// ---- scratch ----
__device__ float g_T[2*8*64*64];
__device__ float g_norm[2*8*64];
__device__ float g_We[8*256*64];       // W_x(head) @ W_slice folded (fp32)
__device__ float g_be[8*64];

__global__ void prep_kernel(const float* __restrict__ W_x, const float* __restrict__ b_x,
                            const float* __restrict__ W_slice, const float* __restrict__ b_slice) {
    int idx = blockIdx.x * blockDim.x + threadIdx.x;
    if (idx < 2*8*64*64) g_T[idx] = 0.f;
    if (idx < 2*8*64)    g_norm[idx] = 0.f;
    if (idx < 8*256*64) {
        int s = idx & 63, c = (idx >> 6) & 255, h = idx >> 14;
        float acc = 0.f;
        #pragma unroll
        for (int d = 0; d < 64; d++)
            acc += W_x[c*512 + h*64 + d] * W_slice[d*64 + s];
        g_We[idx] = acc;
    }
    if (idx < 8*64) {
        int s = idx & 63, h = idx >> 6;
        float acc = b_slice[s];
        #pragma unroll
        for (int d = 0; d < 64; d++)
            acc += b_x[h*64 + d] * W_slice[d*64 + s];
        g_be[idx] = acc;
    }
}

__device__ __forceinline__ uint32_t f2tf(float f) {
    uint32_t u;
    asm("cvt.rna.tf32.f32 %0, %1;" : "=r"(u) : "f"(f));
    return u;
}
__device__ __forceinline__ void mma_tf32(float* c, const uint32_t* a, const uint32_t* b) {
    asm volatile("mma.sync.aligned.m16n8k8.row.col.f32.tf32.tf32.f32 "
                 "{%0,%1,%2,%3},{%4,%5,%6,%7},{%8,%9},{%0,%1,%2,%3};"
                 : "+f"(c[0]), "+f"(c[1]), "+f"(c[2]), "+f"(c[3])
                 : "r"(a[0]), "r"(a[1]), "r"(a[2]), "r"(a[3]), "r"(b[0]), "r"(b[1]));
}
__device__ __forceinline__ void mma_f16(float* c, const uint32_t* a, const uint32_t* b) {
    asm volatile("mma.sync.aligned.m16n8k16.row.col.f32.f16.f16.f32 "
                 "{%0,%1,%2,%3},{%4,%5,%6,%7},{%8,%9},{%0,%1,%2,%3};"
                 : "+f"(c[0]), "+f"(c[1]), "+f"(c[2]), "+f"(c[3])
                 : "r"(a[0]), "r"(a[1]), "r"(a[2]), "r"(a[3]), "r"(b[0]), "r"(b[1]));
}
__device__ __forceinline__ uint32_t h2u(__half2 h) {
    return *(uint32_t*)&h;
}

// SMEM layout (32-bit words):
//  sWe2  [128 kp][72] half2 @ 0      (9216)
//  sWfx2 [128 kp][72] half2 @ 9216   (9216)
//  sX2   [32 tok][132] half2 @ 18432 (4224)
//  sF    [32][72] tf32 bits @ 22656  (2304)
//  sWf   [32][72] fp32 logits -> tf32 weights @ 24960 (2304)
//  sBe   [64] @ 27264
//  sBfx  [64] @ 27328
#define SMEM_WORDS 27392   // 109568 bytes -> 2 CTAs/SM

extern __shared__ float sm[];

__global__ void __launch_bounds__(256, 2)
fused_kernel(const float* __restrict__ x, const float* __restrict__ W_fx,
             const float* __restrict__ b_fx, const float* __restrict__ temperature) {
    uint32_t* sWe2  = (uint32_t*)sm;
    uint32_t* sWfx2 = (uint32_t*)sm + 9216;
    uint32_t* sX2   = (uint32_t*)sm + 18432;
    float* sF   = sm + 22656;
    float* sWf  = sm + 24960;
    float* sBe  = sm + 27264;
    float* sBfx = sm + 27328;
    uint32_t* sFu = (uint32_t*)sF;
    uint32_t* sWu = (uint32_t*)sWf;

    const int tid  = threadIdx.x;
    const int pair = blockIdx.x / PC;      // b*8 + h
    const int cidx = blockIdx.x % PC;
    const int b = pair >> 3, h = pair & 7;

    // stage weights as half2 pairs along k: W2[kp][n] = (w[2kp][n], w[2kp+1][n])
    for (int g = tid; g < 8192; g += 256) {
        int kp = g >> 6, n = g & 63;
        sWe2[kp*72 + n] = h2u(__floats2half2_rn(g_We[h*16384 + (2*kp)*64 + n],
                                                g_We[h*16384 + (2*kp+1)*64 + n]));
        sWfx2[kp*72 + n] = h2u(__floats2half2_rn(W_fx[(2*kp)*512 + h*64 + n],
                                                 W_fx[(2*kp+1)*512 + h*64 + n]));
    }
    if (tid < 64) {
        sBe[tid]  = g_be[h*64 + tid];
        sBfx[tid] = b_fx[h*64 + tid];
    }
    float tmp = temperature[h];
    tmp = fminf(fmaxf(tmp, 0.5f), 5.0f);
    const float invT = 1.0f / tmp;
    __syncthreads();

    const int warp = tid >> 5, lane = tid & 31;
    const int lg4 = lane >> 2, lm4 = lane & 3;

    const int mat = warp >> 2;             // 0: logits(We), 1: fx(Wfx)
    const int n0  = (warp & 3) * 16;
    const uint32_t* sWm = mat ? sWfx2 : sWe2;

    const int mt = warp & 3;               // phase-4 s-tile
    const int nh = warp >> 2;              // phase-4 d-half

    float accT[4][4];
    #pragma unroll
    for (int i = 0; i < 4; i++)
        #pragma unroll
        for (int j = 0; j < 4; j++) accT[i][j] = 0.f;
    float accN = 0.f;

    const float* xbase = x + (size_t)b * N_ * C_;

    for (int chunk = cidx; chunk < NCHUNK; chunk += PC) {
        const float* xp = xbase + (size_t)chunk * TS * C_;

        // ---- phase 1: stage x tile as half2 (tok-major, kp pitch 132) ----
        for (int g = tid; g < 2048; g += 256) {
            float4 v = ((const float4*)xp)[g];
            int row = g >> 6, kp0 = (g & 63) << 1;
            uint2 u;
            u.x = h2u(__floats2half2_rn(v.x, v.y));
            u.y = h2u(__floats2half2_rn(v.z, v.w));
            *(uint2*)&sX2[row*132 + kp0] = u;
        }
        __syncthreads();

        // ---- phase 2: [32 tok] x [16 cols], K=256 via fp16 m16n8k16 ----
        float c2[2][2][4];
        #pragma unroll
        for (int m = 0; m < 2; m++)
            #pragma unroll
            for (int n = 0; n < 2; n++)
                #pragma unroll
                for (int j = 0; j < 4; j++) c2[m][n][j] = 0.f;

        #pragma unroll 8
        for (int ks = 0; ks < 16; ks++) {
            int kc = ks*8 + lm4;
            uint32_t a[2][4];
            a[0][0] = sX2[lg4*132 + kc];
            a[0][1] = sX2[(lg4+8)*132 + kc];
            a[0][2] = sX2[lg4*132 + kc + 4];
            a[0][3] = sX2[(lg4+8)*132 + kc + 4];
            a[1][0] = sX2[(lg4+16)*132 + kc];
            a[1][1] = sX2[(lg4+24)*132 + kc];
            a[1][2] = sX2[(lg4+16)*132 + kc + 4];
            a[1][3] = sX2[(lg4+24)*132 + kc + 4];
            uint32_t bb[2][2];
            int bn = n0 + lg4;
            bb[0][0] = sWm[kc*72 + bn];
            bb[0][1] = sWm[(kc+4)*72 + bn];
            bb[1][0] = sWm[kc*72 + bn + 8];
            bb[1][1] = sWm[(kc+4)*72 + bn + 8];
            mma_f16(c2[0][0], a[0], bb[0]);
            mma_f16(c2[0][1], a[0], bb[1]);
            mma_f16(c2[1][0], a[1], bb[0]);
            mma_f16(c2[1][1], a[1], bb[1]);
        }

        // epilogue: logits -> sWf (raw fp32); fx -> sF (bias added, tf32)
        #pragma unroll
        for (int m = 0; m < 2; m++) {
            #pragma unroll
            for (int nt = 0; nt < 2; nt++) {
                int r = m*16 + lg4;
                int cc = n0 + nt*8 + (lm4 << 1);
                if (mat == 0) {
                    *(float2*)&sWf[r*72 + cc]     = make_float2(c2[m][nt][0], c2[m][nt][1]);
                    *(float2*)&sWf[(r+8)*72 + cc] = make_float2(c2[m][nt][2], c2[m][nt][3]);
                } else {
                    float2 bv = *(float2*)&sBfx[cc];
                    uint2 u0; u0.x = f2tf(c2[m][nt][0] + bv.x); u0.y = f2tf(c2[m][nt][1] + bv.y);
                    uint2 u1; u1.x = f2tf(c2[m][nt][2] + bv.x); u1.y = f2tf(c2[m][nt][3] + bv.y);
                    *(uint2*)&sFu[r*72 + cc]     = u0;
                    *(uint2*)&sFu[(r+8)*72 + cc] = u1;
                }
            }
        }
        __syncthreads();

        // ---- phase 3: softmax over 64 slices (warp handles 4 tokens) ----
        {
            float2 be = *(float2*)&sBe[lane << 1];
            #pragma unroll
            for (int i = 0; i < 4; i++) {
                int t = warp*4 + i;
                float2 lg = *(float2*)&sWf[t*72 + (lane << 1)];
                float l0 = (lg.x + be.x) * invT;
                float l1 = (lg.y + be.y) * invT;
                float m = fmaxf(l0, l1);
                #pragma unroll
                for (int off = 16; off; off >>= 1)
                    m = fmaxf(m, __shfl_xor_sync(0xffffffffu, m, off));
                float e0 = __expf(l0 - m), e1 = __expf(l1 - m);
                float ss = e0 + e1;
                #pragma unroll
                for (int off = 16; off; off >>= 1)
                    ss += __shfl_xor_sync(0xffffffffu, ss, off);
                float inv = __frcp_rn(ss);
                uint2 w2; w2.x = f2tf(e0 * inv); w2.y = f2tf(e1 * inv);
                *(uint2*)&sWu[t*72 + (lane << 1)] = w2;
            }
        }
        __syncthreads();

        // ---- phase 4: T[s][d] += W^T @ F via tf32 mma (acc persists in regs) ----
        #pragma unroll
        for (int k0 = 0; k0 < 32; k0 += 8) {
            uint32_t a[4];
            int at = k0 + lm4, as_ = mt*16 + lg4;
            a[0] = sWu[at*72 + as_];
            a[1] = sWu[at*72 + as_ + 8];
            a[2] = sWu[(at+4)*72 + as_];
            a[3] = sWu[(at+4)*72 + as_ + 8];
            #pragma unroll
            for (int nt = 0; nt < 4; nt++) {
                int d0 = nh*32 + nt*8 + lg4;
                uint32_t bb[2];
                bb[0] = sFu[at*72 + d0];
                bb[1] = sFu[(at+4)*72 + d0];
                mma_tf32(accT[nt], a, bb);
            }
        }
        // slice-norm partial sums (tf32 bits are exact fp32 values)
        if (tid < 64) {
            #pragma unroll 8
            for (int t = 0; t < 32; t++) accN += __uint_as_float(sWu[t*72 + tid]);
        }
        __syncthreads();
    }

    // ---- flush partials ----
    float* dst = g_T + pair * 4096;
    #pragma unroll
    for (int nt = 0; nt < 4; nt++) {
        int s0 = mt*16 + lg4;
        int d0 = nh*32 + nt*8 + (lm4 << 1);
        atomicAdd(&dst[s0*64 + d0],        accT[nt][0]);
        atomicAdd(&dst[s0*64 + d0 + 1],    accT[nt][1]);
        atomicAdd(&dst[(s0+8)*64 + d0],    accT[nt][2]);
        atomicAdd(&dst[(s0+8)*64 + d0+1],  accT[nt][3]);
    }
    if (tid < 64) atomicAdd(&g_norm[pair*64 + tid], accN);
}

// K2: final normalization
__global__ void norm_kernel(float* __restrict__ out) {
    int idx = blockIdx.x * blockDim.x + threadIdx.x;
    int ps = idx >> 6;
    out[idx] = g_T[idx] / (g_norm[ps] + 0.01f);
}

extern "C" void kernel_launch(void* const* d_in, const int* in_sizes, int n_in,
                              void* d_out, int out_size) {
    const float* x    = (const float*)d_in[0];
    const float* W_x  = (const float*)d_in[1];
    const float* b_x  = (const float*)d_in[2];
    const float* W_fx = (const float*)d_in[3];
    const float* b_fx = (const float*)d_in[4];
    const float* W_s  = (const float*)d_in[5];
    const float* b_s  = (const float*)d_in[6];
    const float* temp = (const float*)d_in[7];
    float* out = (float*)d_out;

    cudaFuncSetAttribute(fused_kernel, cudaFuncAttributeMaxDynamicSharedMemorySize,
                         SMEM_WORDS * (int)sizeof(float));

    prep_kernel<<<512, 256>>>(W_x, b_x, W_s, b_s);
    fused_kernel<<<16 * PC, 256, SMEM_WORDS * sizeof(float)>>>(x, W_fx, b_fx, temp);
    norm_kernel<<<256, 256>>>(out);
}

// round 9
// speedup vs baseline: 5.0591x; 1.0395x over previous
#include <cuda_runtime.h>
#include <cuda_fp16.h>
#include <cstdint>

#define B_ 2
#define N_ 65536
#define C_ 256
#define TS 32            // tokens per chunk
#define PC 37            // CTAs per (b,h) pair -> 592 CTAs
#define NCHUNK (N_/TS)   // 2048

// ---- scratch ----
__device__ float g_T[2*8*64*64];
__device__ float g_norm[2*8*64];
__device__ float g_We[8*256*64];       // W_x(head) @ W_slice folded (fp32)
__device__ float g_be[8*64];

__global__ void prep_kernel(const float* __restrict__ W_x, const float* __restrict__ b_x,
                            const float* __restrict__ W_slice, const float* __restrict__ b_slice) {
    int idx = blockIdx.x * blockDim.x + threadIdx.x;
    if (idx < 2*8*64*64) g_T[idx] = 0.f;
    if (idx < 2*8*64)    g_norm[idx] = 0.f;
    if (idx < 8*256*64) {
        int s = idx & 63, c = (idx >> 6) & 255, h = idx >> 14;
        float acc = 0.f;
        #pragma unroll
        for (int d = 0; d < 64; d++)
            acc += W_x[c*512 + h*64 + d] * W_slice[d*64 + s];
        g_We[idx] = acc;
    }
    if (idx < 8*64) {
        int s = idx & 63, h = idx >> 6;
        float acc = b_slice[s];
        #pragma unroll
        for (int d = 0; d < 64; d++)
            acc += b_x[h*64 + d] * W_slice[d*64 + s];
        g_be[idx] = acc;
    }
}

__device__ __forceinline__ void mma_f16(float* c, const uint32_t* a, const uint32_t* b) {
    asm volatile("mma.sync.aligned.m16n8k16.row.col.f32.f16.f16.f32 "
                 "{%0,%1,%2,%3},{%4,%5,%6,%7},{%8,%9},{%0,%1,%2,%3};"
                 : "+f"(c[0]), "+f"(c[1]), "+f"(c[2]), "+f"(c[3])
                 : "r"(a[0]), "r"(a[1]), "r"(a[2]), "r"(a[3]), "r"(b[0]), "r"(b[1]));
}
__device__ __forceinline__ void ldsm4(uint32_t* r, uint32_t addr) {
    asm volatile("ldmatrix.sync.aligned.m8n8.x4.shared.b16 {%0,%1,%2,%3}, [%4];"
        : "=r"(r[0]), "=r"(r[1]), "=r"(r[2]), "=r"(r[3]) : "r"(addr));
}
__device__ __forceinline__ void ldsm4t(uint32_t* r, uint32_t addr) {
    asm volatile("ldmatrix.sync.aligned.m8n8.x4.trans.shared.b16 {%0,%1,%2,%3}, [%4];"
        : "=r"(r[0]), "=r"(r[1]), "=r"(r[2]), "=r"(r[3]) : "r"(addr));
}
__device__ __forceinline__ uint32_t h2u(__half2 h) { return *(uint32_t*)&h; }
__device__ __forceinline__ uint32_t smem_u32(const void* p) {
    uint32_t a;
    asm("{ .reg .u64 t; cvta.to.shared.u64 t, %1; cvt.u32.u64 %0, t; }" : "=r"(a) : "l"(p));
    return a;
}

// SMEM layout (32-bit words):
//  sWe2  [64 n][132 kp] half2  @ 0       (8448)
//  sWfx2 [64 n][132 kp] half2  @ 8448    (8448)
//  sX2   [32 tok][132 kp] half2 @ 16896  (4224)
//  sWh   [32 t][72 s] half     @ 21120   (1152)
//  sFh   [32 t][72 d] half     @ 22272   (1152)
//  sLG   [32 t][72 s] fp32     @ 23424   (2304)
//  sBe   [64] @ 25728
//  sBfx  [64] @ 25792
#define OW_WE   0
#define OW_WFX  8448
#define OW_X    16896
#define OW_WH   21120
#define OW_FH   22272
#define OW_LG   23424
#define OW_BE   25728
#define OW_BFX  25792
#define SMEM_WORDS 25856   // 103424 bytes -> 2 CTAs/SM

extern __shared__ float sm[];

__global__ void __launch_bounds__(256, 2)
fused_kernel(const float* __restrict__ x, const float* __restrict__ W_fx,
             const float* __restrict__ b_fx, const float* __restrict__ temperature) {
    uint32_t* sWe2  = (uint32_t*)sm + OW_WE;
    uint32_t* sWfx2 = (uint32_t*)sm + OW_WFX;
    uint32_t* sX2   = (uint32_t*)sm + OW_X;
    __half*   sWh   = (__half*)(sm + OW_WH);
    __half*   sFh   = (__half*)(sm + OW_FH);
    float*    sLG   = sm + OW_LG;
    float*    sBe   = sm + OW_BE;
    float*    sBfx  = sm + OW_BFX;

    const int tid  = threadIdx.x;
    const int pair = blockIdx.x / PC;      // b*8 + h
    const int cidx = blockIdx.x % PC;
    const int b = pair >> 3, h = pair & 7;

    // stage weights n-major as half2 along k: W2[n][kp] = (w[2kp][n], w[2kp+1][n])
    for (int g = tid; g < 8192; g += 256) {
        int n = g & 63, kp = g >> 6;
        sWe2[n*132 + kp] = h2u(__floats2half2_rn(g_We[h*16384 + (2*kp)*64 + n],
                                                 g_We[h*16384 + (2*kp+1)*64 + n]));
        sWfx2[n*132 + kp] = h2u(__floats2half2_rn(W_fx[(2*kp)*512 + h*64 + n],
                                                  W_fx[(2*kp+1)*512 + h*64 + n]));
    }
    if (tid < 64) {
        sBe[tid]  = g_be[h*64 + tid];
        sBfx[tid] = b_fx[h*64 + tid];
    }
    float tmp = temperature[h];
    tmp = fminf(fmaxf(tmp, 0.5f), 5.0f);
    const float invT = 1.0f / tmp;
    __syncthreads();

    const int warp = tid >> 5, lane = tid & 31;
    const int lg4 = lane >> 2, lm4 = lane & 3;

    const int mat = warp >> 2;             // 0: logits(We), 1: fx(Wfx)
    const int n0  = (warp & 3) * 16;

    const int mt = warp & 3;               // phase-4 s-tile
    const int nh = warp >> 2;              // phase-4 d-half

    // ---- ldmatrix per-lane addresses (bytes, shared space) ----
    const uint32_t sb = smem_u32(sm);
    const int Lm  = lane & 15;
    const int hiK = lane >> 4;             // k-half selector for x4 loads
    // phase-2 A: sX2[tok][kp], rows tok = T0 + Lm, kp offset hiK*4 (+ks*8)
    const uint32_t aA = sb + (uint32_t)(OW_X + Lm*132 + hiK*4) * 4u;
    // phase-2 B: sW[n][kp], rows n = n0 + Lm
    const uint32_t aB = sb + (uint32_t)((mat ? OW_WFX : OW_WE) + (n0 + Lm)*132 + hiK*4) * 4u;
    // phase-4 (trans, half buffers): row t = (lane>>4)*8 + (lane&7), col-octet (lane>>3)&1
    const int tRow = ((lane >> 4) << 3) + (lane & 7);
    const int oct  = (lane >> 3) & 1;
    const uint32_t aW4 = sb + (uint32_t)(OW_WH)*4u + (uint32_t)(tRow*72 + mt*16 + oct*8) * 2u;
    const uint32_t aF4 = sb + (uint32_t)(OW_FH)*4u + (uint32_t)(tRow*72 + nh*32 + oct*8) * 2u;

    float accT[4][4];
    #pragma unroll
    for (int i = 0; i < 4; i++)
        #pragma unroll
        for (int j = 0; j < 4; j++) accT[i][j] = 0.f;
    float accN = 0.f;

    const float* xbase = x + (size_t)b * N_ * C_;

    for (int chunk = cidx; chunk < NCHUNK; chunk += PC) {
        const float* xp = xbase + (size_t)chunk * TS * C_;

        // ---- phase 1: stage x tile as half2 (tok-major, kp pitch 132) ----
        for (int g = tid; g < 2048; g += 256) {
            float4 v = ((const float4*)xp)[g];
            int row = g >> 6, kp0 = (g & 63) << 1;
            uint2 u;
            u.x = h2u(__floats2half2_rn(v.x, v.y));
            u.y = h2u(__floats2half2_rn(v.z, v.w));
            *(uint2*)&sX2[row*132 + kp0] = u;
        }
        __syncthreads();

        // ---- phase 2: [32 tok] x [16 cols], K=256, fragments via ldmatrix ----
        float c2[2][2][4];
        #pragma unroll
        for (int m = 0; m < 2; m++)
            #pragma unroll
            for (int n = 0; n < 2; n++)
                #pragma unroll
                for (int j = 0; j < 4; j++) c2[m][n][j] = 0.f;

        #pragma unroll
        for (int ks = 0; ks < 16; ks++) {
            uint32_t A0[4], A1[4], Bv[4];
            ldsm4(A0, aA + ks*32u);
            ldsm4(A1, aA + ks*32u + 16u*132u*4u);
            ldsm4(Bv, aB + ks*32u);
            uint32_t b0[2] = { Bv[0], Bv[2] };
            uint32_t b1[2] = { Bv[1], Bv[3] };
            mma_f16(c2[0][0], A0, b0);
            mma_f16(c2[0][1], A0, b1);
            mma_f16(c2[1][0], A1, b0);
            mma_f16(c2[1][1], A1, b1);
        }

        // epilogue: logits -> sLG (fp32); fx -> sFh (half [t][d], bias added)
        #pragma unroll
        for (int m = 0; m < 2; m++) {
            #pragma unroll
            for (int nt = 0; nt < 2; nt++) {
                int r = m*16 + lg4;
                int cc = n0 + nt*8 + (lm4 << 1);
                if (mat == 0) {
                    *(float2*)&sLG[r*72 + cc]     = make_float2(c2[m][nt][0], c2[m][nt][1]);
                    *(float2*)&sLG[(r+8)*72 + cc] = make_float2(c2[m][nt][2], c2[m][nt][3]);
                } else {
                    float2 bv = *(float2*)&sBfx[cc];
                    *(uint32_t*)&sFh[r*72 + cc] =
                        h2u(__floats2half2_rn(c2[m][nt][0] + bv.x, c2[m][nt][1] + bv.y));
                    *(uint32_t*)&sFh[(r+8)*72 + cc] =
                        h2u(__floats2half2_rn(c2[m][nt][2] + bv.x, c2[m][nt][3] + bv.y));
                }
            }
        }
        __syncthreads();

        // ---- phase 3: softmax over 64 slices (warp handles 4 tokens) ----
        {
            float2 be = *(float2*)&sBe[lane << 1];
            #pragma unroll
            for (int i = 0; i < 4; i++) {
                int t = warp*4 + i;
                float2 lg = *(float2*)&sLG[t*72 + (lane << 1)];
                float l0 = (lg.x + be.x) * invT;
                float l1 = (lg.y + be.y) * invT;
                float m = fmaxf(l0, l1);
                #pragma unroll
                for (int off = 16; off; off >>= 1)
                    m = fmaxf(m, __shfl_xor_sync(0xffffffffu, m, off));
                float e0 = __expf(l0 - m), e1 = __expf(l1 - m);
                float ss = e0 + e1;
                #pragma unroll
                for (int off = 16; off; off >>= 1)
                    ss += __shfl_xor_sync(0xffffffffu, ss, off);
                float inv = __frcp_rn(ss);
                *(uint32_t*)&sWh[t*72 + (lane << 1)] =
                    h2u(__floats2half2_rn(e0 * inv, e1 * inv));
            }
        }
        __syncthreads();

        // ---- phase 4: T[s][d] += W^T @ F via fp16 mma, fragments via ldmatrix.trans ----
        #pragma unroll
        for (int kstep = 0; kstep < 2; kstep++) {
            uint32_t kb = (uint32_t)(kstep * 16 * 72 * 2);
            uint32_t Aw[4], F0[4], F1[4];
            ldsm4t(Aw, aW4 + kb);
            ldsm4t(F0, aF4 + kb);
            ldsm4t(F1, aF4 + kb + 16u*2u);
            uint32_t fb0[2] = { F0[0], F0[2] };
            uint32_t fb1[2] = { F0[1], F0[3] };
            uint32_t fb2[2] = { F1[0], F1[2] };
            uint32_t fb3[2] = { F1[1], F1[3] };
            mma_f16(accT[0], Aw, fb0);
            mma_f16(accT[1], Aw, fb1);
            mma_f16(accT[2], Aw, fb2);
            mma_f16(accT[3], Aw, fb3);
        }
        // slice-norm partial sums (same fp16 w values as phase 4 -> consistent)
        if (tid < 64) {
            #pragma unroll 8
            for (int t = 0; t < 32; t++) accN += __half2float(sWh[t*72 + tid]);
        }
        __syncthreads();
    }

    // ---- flush partials ----
    float* dst = g_T + pair * 4096;
    #pragma unroll
    for (int nt = 0; nt < 4; nt++) {
        int s0 = mt*16 + lg4;
        int d0 = nh*32 + nt*8 + (lm4 << 1);
        atomicAdd(&dst[s0*64 + d0],        accT[nt][0]);
        atomicAdd(&dst[s0*64 + d0 + 1],    accT[nt][1]);
        atomicAdd(&dst[(s0+8)*64 + d0],    accT[nt][2]);
        atomicAdd(&dst[(s0+8)*64 + d0+1],  accT[nt][3]);
    }
    if (tid < 64) atomicAdd(&g_norm[pair*64 + tid], accN);
}

// K2: final normalization
__global__ void norm_kernel(float* __restrict__ out) {
    int idx = blockIdx.x * blockDim.x + threadIdx.x;
    int ps = idx >> 6;
    out[idx] = g_T[idx] / (g_norm[ps] + 0.01f);
}

extern "C" void kernel_launch(void* const* d_in, const int* in_sizes, int n_in,
                              void* d_out, int out_size) {
    const float* x    = (const float*)d_in[0];
    const float* W_x  = (const float*)d_in[1];
    const float* b_x  = (const float*)d_in[2];
    const float* W_fx = (const float*)d_in[3];
    const float* b_fx = (const float*)d_in[4];
    const float* W_s  = (const float*)d_in[5];
    const float* b_s  = (const float*)d_in[6];
    const float* temp = (const float*)d_in[7];
    float* out = (float*)d_out;

    cudaFuncSetAttribute(fused_kernel, cudaFuncAttributeMaxDynamicSharedMemorySize,
                         SMEM_WORDS * (int)sizeof(float));

    prep_kernel<<<512, 256>>>(W_x, b_x, W_s, b_s);
    fused_kernel<<<16 * PC, 256, SMEM_WORDS * sizeof(float)>>>(x, W_fx, b_fx, temp);
    norm_kernel<<<256, 256>>>(out);
}